// round 3
// baseline (speedup 1.0000x reference)
#include <cuda_runtime.h>

// Problem constants (fixed by the dataset)
#define NNODES 50000
#define NEDGES 800000
#define DIN    256
#define DHID   128
#define DOUT   64

// ---------------- static device scratch (no allocation allowed) --------------
__device__ float g_bufA[NNODES * DHID];
__device__ float g_bufB[NNODES * DHID];
__device__ float g_bufC[NNODES * DOUT];
__device__ int   g_deg_in[NNODES];
__device__ int   g_deg_out[NNODES];
__device__ int   g_cursor[NNODES];
__device__ int   g_rowptr[NNODES + 1];
__device__ int   g_adj[NEDGES];
__device__ float g_ns[NNODES];
__device__ float g_nd[NNODES];

// ---------------- CSR build ---------------------------------------------------
__global__ void zero_int3_kernel() {
    int i = blockIdx.x * blockDim.x + threadIdx.x;
    if (i < NNODES) { g_deg_in[i] = 0; g_deg_out[i] = 0; g_cursor[i] = 0; }
}

__global__ void degree_kernel(const int* __restrict__ src, const int* __restrict__ dst) {
    int e = blockIdx.x * blockDim.x + threadIdx.x;
    if (e < NEDGES) {
        atomicAdd(&g_deg_out[src[e]], 1);
        atomicAdd(&g_deg_in[dst[e]], 1);
    }
}

__global__ void norm_kernel() {
    int i = blockIdx.x * blockDim.x + threadIdx.x;
    if (i < NNODES) {
        g_ns[i] = rsqrtf((float)max(g_deg_out[i], 1));
        g_nd[i] = rsqrtf((float)max(g_deg_in[i], 1));
    }
}

// single-block exclusive scan of deg_in -> rowptr
__global__ void scan_kernel() {
    __shared__ int sums[1024];
    const int t = threadIdx.x;
    const int CH = (NNODES + 1023) / 1024;   // 49
    int begin = t * CH;
    int end = begin + CH; if (end > NNODES) end = NNODES;
    if (begin > NNODES) begin = NNODES;
    int s = 0;
    for (int i = begin; i < end; ++i) s += g_deg_in[i];
    sums[t] = s;
    __syncthreads();
    // Kogge-Stone inclusive scan
    for (int off = 1; off < 1024; off <<= 1) {
        int v = 0;
        if (t >= off) v = sums[t - off];
        __syncthreads();
        if (t >= off) sums[t] += v;
        __syncthreads();
    }
    int run = (t == 0) ? 0 : sums[t - 1];
    for (int i = begin; i < end; ++i) { g_rowptr[i] = run; run += g_deg_in[i]; }
    if (t == 1023) g_rowptr[NNODES] = sums[1023];
}

__global__ void fill_csr_kernel(const int* __restrict__ src, const int* __restrict__ dst) {
    int e = blockIdx.x * blockDim.x + threadIdx.x;
    if (e < NEDGES) {
        int d = dst[e];
        int p = atomicAdd(&g_cursor[d], 1);
        g_adj[g_rowptr[d] + p] = src[e];
    }
}

// ---------------- dense GEMM: C[m,n] = rowscale[m] * sum_k A[m,k]*B[k,n] -----
// BM=128, BK=16, TM=8; 256 threads; BN/TN templated (128/8 and 64/4).
template <int BN, int TN>
__global__ void __launch_bounds__(256)
gemm_kernel(const float* __restrict__ A, const float* __restrict__ B,
            float* __restrict__ C, const float* __restrict__ rowscale,
            int M, int K, int N) {
    constexpr int BM = 128, BK = 16, TM = 8;
    __shared__ float As[BK][BM];   // stored transposed for column reads
    __shared__ float Bs[BK][BN];

    const int tid = threadIdx.x;
    const int tx = tid % (BN / TN);   // 16
    const int ty = tid / (BN / TN);   // 16
    const int blockRow = blockIdx.x * BM;

    float acc[TM][TN];
#pragma unroll
    for (int i = 0; i < TM; ++i)
#pragma unroll
        for (int j = 0; j < TN; ++j) acc[i][j] = 0.0f;

    for (int k0 = 0; k0 < K; k0 += BK) {
        // load A tile: BM*BK floats = 512 float4; 2 per thread
#pragma unroll
        for (int l = 0; l < (BM * BK / 4) / 256; ++l) {
            int idx = tid + l * 256;
            int r = idx / (BK / 4);     // 0..127
            int kq = idx % (BK / 4);    // 0..3
            int row = blockRow + r;
            float4 v = make_float4(0.f, 0.f, 0.f, 0.f);
            if (row < M) v = *(const float4*)&A[(long)row * K + k0 + kq * 4];
            As[kq * 4 + 0][r] = v.x;
            As[kq * 4 + 1][r] = v.y;
            As[kq * 4 + 2][r] = v.z;
            As[kq * 4 + 3][r] = v.w;
        }
        // load B tile: BK*BN floats
#pragma unroll
        for (int l = 0; l < (BK * BN / 4) / 256; ++l) {
            int idx = tid + l * 256;
            int r = idx / (BN / 4);
            int cq = idx % (BN / 4);
            *(float4*)&Bs[r][cq * 4] = *(const float4*)&B[(long)(k0 + r) * N + cq * 4];
        }
        __syncthreads();

#pragma unroll
        for (int k = 0; k < BK; ++k) {
            float a[TM], b[TN];
            float4 a0 = *(const float4*)&As[k][ty * TM];
            float4 a1 = *(const float4*)&As[k][ty * TM + 4];
            a[0] = a0.x; a[1] = a0.y; a[2] = a0.z; a[3] = a0.w;
            a[4] = a1.x; a[5] = a1.y; a[6] = a1.z; a[7] = a1.w;
#pragma unroll
            for (int j = 0; j < TN; j += 4) {
                float4 bv = *(const float4*)&Bs[k][tx * TN + j];
                b[j] = bv.x; b[j + 1] = bv.y; b[j + 2] = bv.z; b[j + 3] = bv.w;
            }
#pragma unroll
            for (int i = 0; i < TM; ++i)
#pragma unroll
                for (int j = 0; j < TN; ++j) acc[i][j] += a[i] * b[j];
        }
        __syncthreads();
    }

#pragma unroll
    for (int i = 0; i < TM; ++i) {
        int m = blockRow + ty * TM + i;
        if (m < M) {
            float s = rowscale ? rowscale[m] : 1.0f;
#pragma unroll
            for (int j = 0; j < TN; j += 4) {
                float4 v;
                v.x = acc[i][j + 0] * s;
                v.y = acc[i][j + 1] * s;
                v.z = acc[i][j + 2] * s;
                v.w = acc[i][j + 3] * s;
                *(float4*)&C[(long)m * N + tx * TN + j] = v;
            }
        }
    }
}

// ---------------- propagation (CSR gather, one warp per node) ----------------
// in is pre-scaled by ns.  out = postscale * (nd*agg + bias)
// postscale = ns (for chained props) or 1 (final).
__global__ void __launch_bounds__(256)
prop128_kernel(const float* __restrict__ in, float* __restrict__ out,
               const float* __restrict__ bias, int do_ns) {
    int warp = (blockIdx.x * blockDim.x + threadIdx.x) >> 5;
    int lane = threadIdx.x & 31;
    if (warp >= NNODES) return;
    int start = g_rowptr[warp];
    int end = g_rowptr[warp + 1];
    const float4* __restrict__ in4 = (const float4*)in;

    float4 acc = make_float4(0.f, 0.f, 0.f, 0.f);
    int e = start;
    for (; e + 3 < end; e += 4) {
        int s0 = __ldg(&g_adj[e + 0]);
        int s1 = __ldg(&g_adj[e + 1]);
        int s2 = __ldg(&g_adj[e + 2]);
        int s3 = __ldg(&g_adj[e + 3]);
        float4 v0 = __ldg(&in4[s0 * 32 + lane]);
        float4 v1 = __ldg(&in4[s1 * 32 + lane]);
        float4 v2 = __ldg(&in4[s2 * 32 + lane]);
        float4 v3 = __ldg(&in4[s3 * 32 + lane]);
        acc.x += v0.x + v1.x + v2.x + v3.x;
        acc.y += v0.y + v1.y + v2.y + v3.y;
        acc.z += v0.z + v1.z + v2.z + v3.z;
        acc.w += v0.w + v1.w + v2.w + v3.w;
    }
    for (; e < end; ++e) {
        int s = __ldg(&g_adj[e]);
        float4 v = __ldg(&in4[s * 32 + lane]);
        acc.x += v.x; acc.y += v.y; acc.z += v.z; acc.w += v.w;
    }
    float nd = g_nd[warp];
    float4 o;
    o.x = acc.x * nd; o.y = acc.y * nd; o.z = acc.z * nd; o.w = acc.w * nd;
    if (bias) {
        float4 bv = *(const float4*)&bias[lane * 4];
        o.x += bv.x; o.y += bv.y; o.z += bv.z; o.w += bv.w;
    }
    if (do_ns) {
        float t = g_ns[warp];
        o.x *= t; o.y *= t; o.z *= t; o.w *= t;
    }
    ((float4*)out)[warp * 32 + lane] = o;
}

__global__ void __launch_bounds__(256)
prop64_kernel(const float* __restrict__ in, float* __restrict__ out,
              const float* __restrict__ bias) {
    int warp = (blockIdx.x * blockDim.x + threadIdx.x) >> 5;
    int lane = threadIdx.x & 31;
    if (warp >= NNODES) return;
    int start = g_rowptr[warp];
    int end = g_rowptr[warp + 1];
    const float2* __restrict__ in2 = (const float2*)in;

    float2 acc = make_float2(0.f, 0.f);
    int e = start;
    for (; e + 3 < end; e += 4) {
        int s0 = __ldg(&g_adj[e + 0]);
        int s1 = __ldg(&g_adj[e + 1]);
        int s2 = __ldg(&g_adj[e + 2]);
        int s3 = __ldg(&g_adj[e + 3]);
        float2 v0 = __ldg(&in2[s0 * 32 + lane]);
        float2 v1 = __ldg(&in2[s1 * 32 + lane]);
        float2 v2 = __ldg(&in2[s2 * 32 + lane]);
        float2 v3 = __ldg(&in2[s3 * 32 + lane]);
        acc.x += v0.x + v1.x + v2.x + v3.x;
        acc.y += v0.y + v1.y + v2.y + v3.y;
    }
    for (; e < end; ++e) {
        int s = __ldg(&g_adj[e]);
        float2 v = __ldg(&in2[s * 32 + lane]);
        acc.x += v.x; acc.y += v.y;
    }
    float nd = g_nd[warp];
    float2 o;
    o.x = acc.x * nd + bias[lane * 2 + 0];
    o.y = acc.y * nd + bias[lane * 2 + 1];
    ((float2*)out)[warp * 32 + lane] = o;
}

// ---------------- launch -----------------------------------------------------
extern "C" void kernel_launch(void* const* d_in, const int* in_sizes, int n_in,
                              void* d_out, int out_size) {
    const float* X   = (const float*)d_in[0];
    const int*   src = (const int*)d_in[1];
    const int*   dst = (const int*)d_in[2];
    const float* W1  = (const float*)d_in[3];
    const float* b1  = (const float*)d_in[4];
    const float* W3  = (const float*)d_in[5];
    const float* b3  = (const float*)d_in[6];
    float* out = (float*)d_out;

    // device-global symbol addresses usable directly from host-launched kernels
    float *bufA, *bufB, *bufC, *nsp;
    cudaGetSymbolAddress((void**)&bufA, g_bufA);
    cudaGetSymbolAddress((void**)&bufB, g_bufB);
    cudaGetSymbolAddress((void**)&bufC, g_bufC);
    cudaGetSymbolAddress((void**)&nsp,  g_ns);

    const int TPB = 256;
    const int edgeGrid = (NEDGES + TPB - 1) / TPB;
    const int nodeGrid = (NNODES + TPB - 1) / TPB;
    const int warpGrid = (NNODES * 32 + TPB - 1) / TPB;   // one warp per node
    const int gemmGrid = (NNODES + 127) / 128;

    // 1. CSR build + norms
    zero_int3_kernel<<<nodeGrid, TPB>>>();
    degree_kernel<<<edgeGrid, TPB>>>(src, dst);
    norm_kernel<<<nodeGrid, TPB>>>();
    scan_kernel<<<1, 1024>>>();
    fill_csr_kernel<<<edgeGrid, TPB>>>(src, dst);

    // 2. GEMM1: bufA = ns ⊙ (X @ W1)
    gemm_kernel<128, 8><<<gemmGrid, 256>>>(X, W1, bufA, nsp, NNODES, DIN, DHID);

    // 3. GraphConv1 prop (+b1) then 4 APPNP props, all kept pre-scaled by ns
    prop128_kernel<<<warpGrid, TPB>>>(bufA, bufB, b1, 1);
    prop128_kernel<<<warpGrid, TPB>>>(bufB, bufA, nullptr, 1);
    prop128_kernel<<<warpGrid, TPB>>>(bufA, bufB, nullptr, 1);
    prop128_kernel<<<warpGrid, TPB>>>(bufB, bufA, nullptr, 1);
    prop128_kernel<<<warpGrid, TPB>>>(bufA, bufB, nullptr, 1);

    // 4. GEMM2: bufC = (ns ⊙ h4) @ W3 == ns ⊙ (h4 @ W3)  (row scale commutes)
    gemm_kernel<64, 4><<<gemmGrid, 256>>>(bufB, W3, bufC, nullptr, NNODES, DHID, DOUT);

    // 5. final prop: out = nd ⊙ (A bufC) + b3
    prop64_kernel<<<warpGrid, TPB>>>(bufC, out, b3);
}

// round 4
// speedup vs baseline: 1.2798x; 1.2798x over previous
#include <cuda_runtime.h>
#include <cuda_fp16.h>

// Problem constants (fixed by the dataset)
#define NNODES 50000
#define NEDGES 800000
#define DIN    256
#define DHID   128
#define DOUT   64
#define SCAN_BLOCKS 196          // ceil(50000/256)

// ---------------- static device scratch (no allocation allowed) --------------
__device__ __half g_hA[NNODES * DHID];
__device__ __half g_hB[NNODES * DHID];
__device__ float  g_bufC[NNODES * DOUT];
__device__ int    g_deg_in[NNODES];
__device__ int    g_deg_out[NNODES];
__device__ int    g_cursor[NNODES];
__device__ int    g_rowptr[NNODES + 1];
__device__ unsigned short g_adj[NEDGES];
__device__ float  g_ns[NNODES];
__device__ float  g_nd[NNODES];
__device__ int    g_blocksum[256];

// ---------------- CSR build ---------------------------------------------------
__global__ void zero_int3_kernel() {
    int i = blockIdx.x * blockDim.x + threadIdx.x;
    if (i < NNODES) { g_deg_in[i] = 0; g_deg_out[i] = 0; g_cursor[i] = 0; }
}

__global__ void degree_kernel(const int* __restrict__ src, const int* __restrict__ dst) {
    int e = blockIdx.x * blockDim.x + threadIdx.x;
    if (e < NEDGES) {
        atomicAdd(&g_deg_out[src[e]], 1);
        atomicAdd(&g_deg_in[dst[e]], 1);
    }
}

// phase 1: per-block exclusive scan of deg_in, block totals to g_blocksum
__global__ void __launch_bounds__(256) scan1_kernel() {
    __shared__ int s[256];
    const int tid = threadIdx.x;
    const int i = blockIdx.x * 256 + tid;
    int v = (i < NNODES) ? g_deg_in[i] : 0;
    s[tid] = v;
    __syncthreads();
#pragma unroll
    for (int off = 1; off < 256; off <<= 1) {
        int t = 0;
        if (tid >= off) t = s[tid - off];
        __syncthreads();
        if (tid >= off) s[tid] += t;
        __syncthreads();
    }
    if (i < NNODES) g_rowptr[i] = s[tid] - v;     // exclusive within block
    if (tid == 255) g_blocksum[blockIdx.x] = s[255];
}

// phase 2: exclusive scan of the 196 block sums (single tiny block)
__global__ void __launch_bounds__(256) scan2_kernel() {
    __shared__ int s[256];
    const int tid = threadIdx.x;
    int v = (tid < SCAN_BLOCKS) ? g_blocksum[tid] : 0;
    s[tid] = v;
    __syncthreads();
#pragma unroll
    for (int off = 1; off < 256; off <<= 1) {
        int t = 0;
        if (tid >= off) t = s[tid - off];
        __syncthreads();
        if (tid >= off) s[tid] += t;
        __syncthreads();
    }
    if (tid < SCAN_BLOCKS) g_blocksum[tid] = s[tid] - v;  // exclusive
}

// phase 3: add block offsets; fuse norm computation; set rowptr[N]
__global__ void __launch_bounds__(256) scan3_norm_kernel() {
    const int i = blockIdx.x * 256 + threadIdx.x;
    if (i < NNODES) {
        g_rowptr[i] += g_blocksum[blockIdx.x];
        g_ns[i] = rsqrtf((float)max(g_deg_out[i], 1));
        g_nd[i] = rsqrtf((float)max(g_deg_in[i], 1));
    }
    if (i == 0) g_rowptr[NNODES] = NEDGES;
}

__global__ void fill_csr_kernel(const int* __restrict__ src, const int* __restrict__ dst) {
    int e = blockIdx.x * blockDim.x + threadIdx.x;
    if (e < NEDGES) {
        int d = dst[e];
        int p = atomicAdd(&g_cursor[d], 1);
        g_adj[g_rowptr[d] + p] = (unsigned short)src[e];
    }
}

// ---------------- typed vector load/store helpers ----------------------------
__device__ __forceinline__ float4 load4(const float* p) { return *(const float4*)p; }
__device__ __forceinline__ float4 load4(const __half* p) {
    uint2 u = *(const uint2*)p;
    float2 a = __half22float2(*reinterpret_cast<__half2*>(&u.x));
    float2 b = __half22float2(*reinterpret_cast<__half2*>(&u.y));
    return make_float4(a.x, a.y, b.x, b.y);
}
__device__ __forceinline__ void store4(float* p, float4 v) { *(float4*)p = v; }
__device__ __forceinline__ void store4(__half* p, float4 v) {
    __half2 a = __floats2half2_rn(v.x, v.y);
    __half2 b = __floats2half2_rn(v.z, v.w);
    uint2 u;
    u.x = *reinterpret_cast<unsigned*>(&a);
    u.y = *reinterpret_cast<unsigned*>(&b);
    *(uint2*)p = u;
}

// ---------------- dense GEMM: C[m,n] = rowscale[m] * sum_k A[m,k]*B[k,n] -----
// BM=128, BK=16, TM=8; 256 threads; templated on A/out types and BN/TN.
template <typename AT, typename OT, int BN, int TN>
__global__ void __launch_bounds__(256)
gemm_kernel(const AT* __restrict__ A, const float* __restrict__ B,
            OT* __restrict__ C, const float* __restrict__ rowscale,
            int M, int K, int N) {
    constexpr int BM = 128, BK = 16, TM = 8;
    __shared__ float As[BK][BM];
    __shared__ float Bs[BK][BN];

    const int tid = threadIdx.x;
    const int tx = tid % (BN / TN);
    const int ty = tid / (BN / TN);
    const int blockRow = blockIdx.x * BM;

    float acc[TM][TN];
#pragma unroll
    for (int i = 0; i < TM; ++i)
#pragma unroll
        for (int j = 0; j < TN; ++j) acc[i][j] = 0.0f;

    for (int k0 = 0; k0 < K; k0 += BK) {
#pragma unroll
        for (int l = 0; l < (BM * BK / 4) / 256; ++l) {
            int idx = tid + l * 256;
            int r = idx / (BK / 4);
            int kq = idx % (BK / 4);
            int row = blockRow + r;
            float4 v = make_float4(0.f, 0.f, 0.f, 0.f);
            if (row < M) v = load4(&A[(long)row * K + k0 + kq * 4]);
            As[kq * 4 + 0][r] = v.x;
            As[kq * 4 + 1][r] = v.y;
            As[kq * 4 + 2][r] = v.z;
            As[kq * 4 + 3][r] = v.w;
        }
#pragma unroll
        for (int l = 0; l < (BK * BN / 4) / 256; ++l) {
            int idx = tid + l * 256;
            int r = idx / (BN / 4);
            int cq = idx % (BN / 4);
            *(float4*)&Bs[r][cq * 4] = *(const float4*)&B[(long)(k0 + r) * N + cq * 4];
        }
        __syncthreads();

#pragma unroll
        for (int k = 0; k < BK; ++k) {
            float a[TM], b[TN];
            float4 a0 = *(const float4*)&As[k][ty * TM];
            float4 a1 = *(const float4*)&As[k][ty * TM + 4];
            a[0] = a0.x; a[1] = a0.y; a[2] = a0.z; a[3] = a0.w;
            a[4] = a1.x; a[5] = a1.y; a[6] = a1.z; a[7] = a1.w;
#pragma unroll
            for (int j = 0; j < TN; j += 4) {
                float4 bv = *(const float4*)&Bs[k][tx * TN + j];
                b[j] = bv.x; b[j + 1] = bv.y; b[j + 2] = bv.z; b[j + 3] = bv.w;
            }
#pragma unroll
            for (int i = 0; i < TM; ++i)
#pragma unroll
                for (int j = 0; j < TN; ++j) acc[i][j] += a[i] * b[j];
        }
        __syncthreads();
    }

#pragma unroll
    for (int i = 0; i < TM; ++i) {
        int m = blockRow + ty * TM + i;
        if (m < M) {
            float s = rowscale ? rowscale[m] : 1.0f;
#pragma unroll
            for (int j = 0; j < TN; j += 4) {
                float4 v;
                v.x = acc[i][j + 0] * s;
                v.y = acc[i][j + 1] * s;
                v.z = acc[i][j + 2] * s;
                v.w = acc[i][j + 3] * s;
                store4(&C[(long)m * N + tx * TN + j], v);
            }
        }
    }
}

// ---------------- propagation, fp16 features (CSR gather, warp per node) -----
// in is pre-scaled by ns.  out = [ns *] (nd*agg + bias), fp32 accumulation.
__global__ void __launch_bounds__(256)
prop128h_kernel(const __half* __restrict__ in, __half* __restrict__ out,
                const float* __restrict__ bias, int do_ns) {
    int warp = (blockIdx.x * blockDim.x + threadIdx.x) >> 5;
    int lane = threadIdx.x & 31;
    if (warp >= NNODES) return;
    int start = g_rowptr[warp];
    int end = g_rowptr[warp + 1];
    const uint2* __restrict__ in2 = (const uint2*)in;   // 4 halves per lane

    float4 acc = make_float4(0.f, 0.f, 0.f, 0.f);
    int e = start;
    for (; e + 3 < end; e += 4) {
        int s0 = g_adj[e + 0];
        int s1 = g_adj[e + 1];
        int s2 = g_adj[e + 2];
        int s3 = g_adj[e + 3];
        uint2 v0 = __ldg(&in2[s0 * 32 + lane]);
        uint2 v1 = __ldg(&in2[s1 * 32 + lane]);
        uint2 v2 = __ldg(&in2[s2 * 32 + lane]);
        uint2 v3 = __ldg(&in2[s3 * 32 + lane]);
        float2 a, b;
        a = __half22float2(*reinterpret_cast<__half2*>(&v0.x));
        b = __half22float2(*reinterpret_cast<__half2*>(&v0.y));
        acc.x += a.x; acc.y += a.y; acc.z += b.x; acc.w += b.y;
        a = __half22float2(*reinterpret_cast<__half2*>(&v1.x));
        b = __half22float2(*reinterpret_cast<__half2*>(&v1.y));
        acc.x += a.x; acc.y += a.y; acc.z += b.x; acc.w += b.y;
        a = __half22float2(*reinterpret_cast<__half2*>(&v2.x));
        b = __half22float2(*reinterpret_cast<__half2*>(&v2.y));
        acc.x += a.x; acc.y += a.y; acc.z += b.x; acc.w += b.y;
        a = __half22float2(*reinterpret_cast<__half2*>(&v3.x));
        b = __half22float2(*reinterpret_cast<__half2*>(&v3.y));
        acc.x += a.x; acc.y += a.y; acc.z += b.x; acc.w += b.y;
    }
    for (; e < end; ++e) {
        int s = g_adj[e];
        uint2 v = __ldg(&in2[s * 32 + lane]);
        float2 a = __half22float2(*reinterpret_cast<__half2*>(&v.x));
        float2 b = __half22float2(*reinterpret_cast<__half2*>(&v.y));
        acc.x += a.x; acc.y += a.y; acc.z += b.x; acc.w += b.y;
    }
    float nd = g_nd[warp];
    float4 o;
    o.x = acc.x * nd; o.y = acc.y * nd; o.z = acc.z * nd; o.w = acc.w * nd;
    if (bias) {
        float4 bv = *(const float4*)&bias[lane * 4];
        o.x += bv.x; o.y += bv.y; o.z += bv.z; o.w += bv.w;
    }
    if (do_ns) {
        float t = g_ns[warp];
        o.x *= t; o.y *= t; o.z *= t; o.w *= t;
    }
    __half2 h0 = __floats2half2_rn(o.x, o.y);
    __half2 h1 = __floats2half2_rn(o.z, o.w);
    uint2 u;
    u.x = *reinterpret_cast<unsigned*>(&h0);
    u.y = *reinterpret_cast<unsigned*>(&h1);
    ((uint2*)out)[warp * 32 + lane] = u;
}

// final prop, fp32 D=64: out = nd*(A in) + b3
__global__ void __launch_bounds__(256)
prop64_kernel(const float* __restrict__ in, float* __restrict__ out,
              const float* __restrict__ bias) {
    int warp = (blockIdx.x * blockDim.x + threadIdx.x) >> 5;
    int lane = threadIdx.x & 31;
    if (warp >= NNODES) return;
    int start = g_rowptr[warp];
    int end = g_rowptr[warp + 1];
    const float2* __restrict__ in2 = (const float2*)in;

    float2 acc = make_float2(0.f, 0.f);
    int e = start;
    for (; e + 3 < end; e += 4) {
        int s0 = g_adj[e + 0];
        int s1 = g_adj[e + 1];
        int s2 = g_adj[e + 2];
        int s3 = g_adj[e + 3];
        float2 v0 = __ldg(&in2[s0 * 32 + lane]);
        float2 v1 = __ldg(&in2[s1 * 32 + lane]);
        float2 v2 = __ldg(&in2[s2 * 32 + lane]);
        float2 v3 = __ldg(&in2[s3 * 32 + lane]);
        acc.x += v0.x + v1.x + v2.x + v3.x;
        acc.y += v0.y + v1.y + v2.y + v3.y;
    }
    for (; e < end; ++e) {
        int s = g_adj[e];
        float2 v = __ldg(&in2[s * 32 + lane]);
        acc.x += v.x; acc.y += v.y;
    }
    float nd = g_nd[warp];
    float2 o;
    o.x = acc.x * nd + bias[lane * 2 + 0];
    o.y = acc.y * nd + bias[lane * 2 + 1];
    ((float2*)out)[warp * 32 + lane] = o;
}

// ---------------- launch -----------------------------------------------------
extern "C" void kernel_launch(void* const* d_in, const int* in_sizes, int n_in,
                              void* d_out, int out_size) {
    const float* X   = (const float*)d_in[0];
    const int*   src = (const int*)d_in[1];
    const int*   dst = (const int*)d_in[2];
    const float* W1  = (const float*)d_in[3];
    const float* b1  = (const float*)d_in[4];
    const float* W3  = (const float*)d_in[5];
    const float* b3  = (const float*)d_in[6];
    float* out = (float*)d_out;

    __half *hA, *hB;
    float *bufC, *nsp;
    cudaGetSymbolAddress((void**)&hA,   g_hA);
    cudaGetSymbolAddress((void**)&hB,   g_hB);
    cudaGetSymbolAddress((void**)&bufC, g_bufC);
    cudaGetSymbolAddress((void**)&nsp,  g_ns);

    const int TPB = 256;
    const int edgeGrid = (NEDGES + TPB - 1) / TPB;
    const int nodeGrid = (NNODES + TPB - 1) / TPB;
    const int warpGrid = (NNODES * 32 + TPB - 1) / TPB;   // one warp per node
    const int gemmGrid = (NNODES + 127) / 128;

    // 1. CSR build + norms (multi-block scan)
    zero_int3_kernel<<<nodeGrid, TPB>>>();
    degree_kernel<<<edgeGrid, TPB>>>(src, dst);
    scan1_kernel<<<SCAN_BLOCKS, 256>>>();
    scan2_kernel<<<1, 256>>>();
    scan3_norm_kernel<<<SCAN_BLOCKS, 256>>>();
    fill_csr_kernel<<<edgeGrid, TPB>>>(src, dst);

    // 2. GEMM1: hA = fp16( ns ⊙ (X @ W1) )
    gemm_kernel<float, __half, 128, 8><<<gemmGrid, 256>>>(X, W1, hA, nsp, NNODES, DIN, DHID);

    // 3. GraphConv1 prop (+b1) then 4 APPNP props, pre-scaled by ns, fp16 storage
    prop128h_kernel<<<warpGrid, TPB>>>(hA, hB, b1, 1);
    prop128h_kernel<<<warpGrid, TPB>>>(hB, hA, nullptr, 1);
    prop128h_kernel<<<warpGrid, TPB>>>(hA, hB, nullptr, 1);
    prop128h_kernel<<<warpGrid, TPB>>>(hB, hA, nullptr, 1);
    prop128h_kernel<<<warpGrid, TPB>>>(hA, hB, nullptr, 1);

    // 4. GEMM2: bufC = (ns ⊙ h4) @ W3 == ns ⊙ (h4 @ W3)  (row scale commutes)
    gemm_kernel<__half, float, 64, 4><<<gemmGrid, 256>>>(hB, W3, bufC, nullptr, NNODES, DHID, DOUT);

    // 5. final prop: out = nd ⊙ (A bufC) + b3
    prop64_kernel<<<warpGrid, TPB>>>(bufC, out, b3);
}

// round 5
// speedup vs baseline: 1.8552x; 1.4496x over previous
#include <cuda_runtime.h>
#include <cuda_fp16.h>
#include <mma.h>

using namespace nvcuda;

// Problem constants (fixed by the dataset)
#define NNODES 50000
#define NEDGES 800000
#define DIN    256
#define DHID   128
#define DOUT   64
#define SCAN_BLOCKS 196          // ceil(50000/256)

// ---------------- static device scratch (no allocation allowed) --------------
__device__ __half g_hA[NNODES * DHID];
__device__ __half g_hB[NNODES * DHID];
__device__ __half g_hC[NNODES * DOUT];
__device__ int    g_deg_in[NNODES];
__device__ int    g_deg_out[NNODES];
__device__ int    g_cursor[NNODES];
__device__ int    g_rowptr[NNODES + 1];
__device__ unsigned short g_adj[NEDGES];
__device__ float  g_ns[NNODES];
__device__ float  g_nd[NNODES];
__device__ int    g_blocksum[256];

// ---------------- CSR build ---------------------------------------------------
__global__ void zero_deg_kernel() {
    int i = blockIdx.x * blockDim.x + threadIdx.x;
    if (i < NNODES) { g_deg_in[i] = 0; g_deg_out[i] = 0; }
}

__global__ void degree_kernel(const int* __restrict__ src, const int* __restrict__ dst) {
    int e = blockIdx.x * blockDim.x + threadIdx.x;
    if (e < NEDGES) {
        atomicAdd(&g_deg_out[src[e]], 1);
        atomicAdd(&g_deg_in[dst[e]], 1);
    }
}

// phase 1: per-block exclusive scan of deg_in, block totals to g_blocksum
__global__ void __launch_bounds__(256) scan1_kernel() {
    __shared__ int s[256];
    const int tid = threadIdx.x;
    const int i = blockIdx.x * 256 + tid;
    int v = (i < NNODES) ? g_deg_in[i] : 0;
    s[tid] = v;
    __syncthreads();
#pragma unroll
    for (int off = 1; off < 256; off <<= 1) {
        int t = 0;
        if (tid >= off) t = s[tid - off];
        __syncthreads();
        if (tid >= off) s[tid] += t;
        __syncthreads();
    }
    if (i < NNODES) g_rowptr[i] = s[tid] - v;     // exclusive within block
    if (tid == 255) g_blocksum[blockIdx.x] = s[255];
}

// phase 2: exclusive scan of the block sums (single tiny block)
__global__ void __launch_bounds__(256) scan2_kernel() {
    __shared__ int s[256];
    const int tid = threadIdx.x;
    int v = (tid < SCAN_BLOCKS) ? g_blocksum[tid] : 0;
    s[tid] = v;
    __syncthreads();
#pragma unroll
    for (int off = 1; off < 256; off <<= 1) {
        int t = 0;
        if (tid >= off) t = s[tid - off];
        __syncthreads();
        if (tid >= off) s[tid] += t;
        __syncthreads();
    }
    if (tid < SCAN_BLOCKS) g_blocksum[tid] = s[tid] - v;  // exclusive
}

// phase 3: add block offsets; seed cursor; fuse norm computation
__global__ void __launch_bounds__(256) scan3_norm_kernel() {
    const int i = blockIdx.x * 256 + threadIdx.x;
    if (i < NNODES) {
        int rp = g_rowptr[i] + g_blocksum[blockIdx.x];
        g_rowptr[i] = rp;
        g_cursor[i] = rp;                         // fill uses cursor directly
        g_ns[i] = rsqrtf((float)max(g_deg_out[i], 1));
        g_nd[i] = rsqrtf((float)max(g_deg_in[i], 1));
    }
    if (i == 0) g_rowptr[NNODES] = NEDGES;
}

__global__ void fill_csr_kernel(const int* __restrict__ src, const int* __restrict__ dst) {
    int e = blockIdx.x * blockDim.x + threadIdx.x;
    if (e < NEDGES) {
        int p = atomicAdd(&g_cursor[dst[e]], 1);
        g_adj[p] = (unsigned short)src[e];
    }
}

// ---------------- GEMM1 (tensor core): hC = fp16( ns ⊙ (X @ W1) ) ------------
// M=50000, K=256, N=128. fp32 inputs converted to fp16 in smem, HMMA fp32 acc.
// 256 threads = 8 warps; block tile 128x128, BK=32; warp tile 64x32 (2x4 warps).
__global__ void __launch_bounds__(256)
gemm1_wmma_kernel(const float* __restrict__ A, const float* __restrict__ B,
                  __half* __restrict__ C, const float* __restrict__ rowscale) {
    constexpr int M = NNODES, K = DIN, N = DHID;
    constexpr int BK = 32;
    __shared__ __half As[128][BK + 8];     // ldm 40 halves (80 B, 16B-mult)
    __shared__ __half Bs[BK][N + 8];       // ldm 136 halves (272 B)
    __shared__ float  Sepi[8][16 * 20];    // per-warp epilogue scratch

    const int tid  = threadIdx.x;
    const int lane = tid & 31;
    const int wid  = tid >> 5;
    const int wm   = wid >> 2;             // 0..1  (64 rows each)
    const int wn   = wid & 3;              // 0..3  (32 cols each)
    const int blockRow = blockIdx.x * 128;

    wmma::fragment<wmma::accumulator, 16, 16, 16, float> facc[4][2];
#pragma unroll
    for (int i = 0; i < 4; ++i)
#pragma unroll
        for (int j = 0; j < 2; ++j) wmma::fill_fragment(facc[i][j], 0.0f);

    for (int k0 = 0; k0 < K; k0 += BK) {
        // A tile: 128x32 fp32 -> half. 4096 floats, 16/thread as 4x float4.
#pragma unroll
        for (int l = 0; l < 4; ++l) {
            int idx = tid + l * 256;       // 0..1023 float4 slots
            int r  = idx >> 3;             // row 0..127
            int q  = idx & 7;              // quad 0..7
            int row = blockRow + r;
            float4 v = make_float4(0.f, 0.f, 0.f, 0.f);
            if (row < M) v = *(const float4*)&A[(long)row * K + k0 + q * 4];
            __half2 h0 = __floats2half2_rn(v.x, v.y);
            __half2 h1 = __floats2half2_rn(v.z, v.w);
            uint2 u;
            u.x = *reinterpret_cast<unsigned*>(&h0);
            u.y = *reinterpret_cast<unsigned*>(&h1);
            *(uint2*)&As[r][q * 4] = u;
        }
        // B tile: 32x128 fp32 -> half. 4096 floats.
#pragma unroll
        for (int l = 0; l < 4; ++l) {
            int idx = tid + l * 256;
            int r = idx >> 5;              // row 0..31
            int q = idx & 31;              // quad 0..31
            float4 v = *(const float4*)&B[(long)(k0 + r) * N + q * 4];
            __half2 h0 = __floats2half2_rn(v.x, v.y);
            __half2 h1 = __floats2half2_rn(v.z, v.w);
            uint2 u;
            u.x = *reinterpret_cast<unsigned*>(&h0);
            u.y = *reinterpret_cast<unsigned*>(&h1);
            *(uint2*)&Bs[r][q * 4] = u;
        }
        __syncthreads();

#pragma unroll
        for (int kk = 0; kk < BK; kk += 16) {
            wmma::fragment<wmma::matrix_a, 16, 16, 16, __half, wmma::row_major> fa[4];
            wmma::fragment<wmma::matrix_b, 16, 16, 16, __half, wmma::row_major> fb[2];
#pragma unroll
            for (int i = 0; i < 4; ++i)
                wmma::load_matrix_sync(fa[i], &As[wm * 64 + i * 16][kk], BK + 8);
#pragma unroll
            for (int j = 0; j < 2; ++j)
                wmma::load_matrix_sync(fb[j], &Bs[kk][wn * 32 + j * 16], N + 8);
#pragma unroll
            for (int i = 0; i < 4; ++i)
#pragma unroll
                for (int j = 0; j < 2; ++j)
                    wmma::mma_sync(facc[i][j], fa[i], fb[j], facc[i][j]);
        }
        __syncthreads();
    }

    // epilogue: scale by ns, convert to fp16, store
    float* scratch = Sepi[wid];
#pragma unroll
    for (int i = 0; i < 4; ++i) {
#pragma unroll
        for (int j = 0; j < 2; ++j) {
            wmma::store_matrix_sync(scratch, facc[i][j], 20, wmma::mem_row_major);
            __syncwarp();
            int r = lane >> 1;
            int c = (lane & 1) * 8;
            int gm = blockRow + wm * 64 + i * 16 + r;
            if (gm < M) {
                float s = rowscale[gm];
                const float* p = &scratch[r * 20 + c];
                __half2 h0 = __floats2half2_rn(p[0] * s, p[1] * s);
                __half2 h1 = __floats2half2_rn(p[2] * s, p[3] * s);
                __half2 h2 = __floats2half2_rn(p[4] * s, p[5] * s);
                __half2 h3 = __floats2half2_rn(p[6] * s, p[7] * s);
                uint4 u;
                u.x = *reinterpret_cast<unsigned*>(&h0);
                u.y = *reinterpret_cast<unsigned*>(&h1);
                u.z = *reinterpret_cast<unsigned*>(&h2);
                u.w = *reinterpret_cast<unsigned*>(&h3);
                *(uint4*)&C[(long)gm * N + wn * 32 + j * 16 + c] = u;
            }
            __syncwarp();
        }
    }
}

// ---------------- GEMM2 (tensor core): hC = (fp16 A) @ fp16(W3) --------------
// M=50000, K=128, N=64. Block tile 128x64, BK=32; warp tile 32x32 (4x2 warps).
__global__ void __launch_bounds__(256)
gemm2_wmma_kernel(const __half* __restrict__ A, const float* __restrict__ B,
                  __half* __restrict__ C) {
    constexpr int M = NNODES, K = DHID, N = DOUT;
    constexpr int BK = 32;
    __shared__ __half As[128][BK + 8];     // ldm 40
    __shared__ __half Bs[BK][N + 8];       // ldm 72 (144 B)
    __shared__ float  Sepi[8][16 * 20];

    const int tid  = threadIdx.x;
    const int lane = tid & 31;
    const int wid  = tid >> 5;
    const int wm   = wid >> 1;             // 0..3 (32 rows each)
    const int wn   = wid & 1;              // 0..1 (32 cols each)
    const int blockRow = blockIdx.x * 128;

    wmma::fragment<wmma::accumulator, 16, 16, 16, float> facc[2][2];
#pragma unroll
    for (int i = 0; i < 2; ++i)
#pragma unroll
        for (int j = 0; j < 2; ++j) wmma::fill_fragment(facc[i][j], 0.0f);

    for (int k0 = 0; k0 < K; k0 += BK) {
        // A tile: 128x32 halves = 4096 halves; 16/thread as 2x uint4 (8 halves)
#pragma unroll
        for (int l = 0; l < 2; ++l) {
            int idx = tid + l * 256;       // 0..511 8-half slots
            int r = idx >> 2;              // row 0..127
            int q = idx & 3;               // 0..3 (8-half groups)
            int row = blockRow + r;
            uint4 u = make_uint4(0, 0, 0, 0);
            if (row < M) u = *(const uint4*)&A[(long)row * K + k0 + q * 8];
            *(uint4*)&As[r][q * 8] = u;
        }
        // B tile: 32x64 fp32 -> half; 2048 floats, 8/thread as 2x float4
#pragma unroll
        for (int l = 0; l < 2; ++l) {
            int idx = tid + l * 256;       // 0..511 float4 slots
            int r = idx >> 4;              // row 0..31
            int q = idx & 15;              // 0..15
            float4 v = *(const float4*)&B[(long)(k0 + r) * N + q * 4];
            __half2 h0 = __floats2half2_rn(v.x, v.y);
            __half2 h1 = __floats2half2_rn(v.z, v.w);
            uint2 u;
            u.x = *reinterpret_cast<unsigned*>(&h0);
            u.y = *reinterpret_cast<unsigned*>(&h1);
            *(uint2*)&Bs[r][q * 4] = u;
        }
        __syncthreads();

#pragma unroll
        for (int kk = 0; kk < BK; kk += 16) {
            wmma::fragment<wmma::matrix_a, 16, 16, 16, __half, wmma::row_major> fa[2];
            wmma::fragment<wmma::matrix_b, 16, 16, 16, __half, wmma::row_major> fb[2];
#pragma unroll
            for (int i = 0; i < 2; ++i)
                wmma::load_matrix_sync(fa[i], &As[wm * 32 + i * 16][kk], BK + 8);
#pragma unroll
            for (int j = 0; j < 2; ++j)
                wmma::load_matrix_sync(fb[j], &Bs[kk][wn * 32 + j * 16], N + 8);
#pragma unroll
            for (int i = 0; i < 2; ++i)
#pragma unroll
                for (int j = 0; j < 2; ++j)
                    wmma::mma_sync(facc[i][j], fa[i], fb[j], facc[i][j]);
        }
        __syncthreads();
    }

    float* scratch = Sepi[wid];
#pragma unroll
    for (int i = 0; i < 2; ++i) {
#pragma unroll
        for (int j = 0; j < 2; ++j) {
            wmma::store_matrix_sync(scratch, facc[i][j], 20, wmma::mem_row_major);
            __syncwarp();
            int r = lane >> 1;
            int c = (lane & 1) * 8;
            int gm = blockRow + wm * 32 + i * 16 + r;
            if (gm < M) {
                const float* p = &scratch[r * 20 + c];
                __half2 h0 = __floats2half2_rn(p[0], p[1]);
                __half2 h1 = __floats2half2_rn(p[2], p[3]);
                __half2 h2 = __floats2half2_rn(p[4], p[5]);
                __half2 h3 = __floats2half2_rn(p[6], p[7]);
                uint4 u;
                u.x = *reinterpret_cast<unsigned*>(&h0);
                u.y = *reinterpret_cast<unsigned*>(&h1);
                u.z = *reinterpret_cast<unsigned*>(&h2);
                u.w = *reinterpret_cast<unsigned*>(&h3);
                *(uint4*)&C[(long)gm * N + wn * 32 + j * 16 + c] = u;
            }
            __syncwarp();
        }
    }
}

// ---------------- propagation, fp16 features (CSR gather, warp per node) -----
__global__ void __launch_bounds__(256)
prop128h_kernel(const __half* __restrict__ in, __half* __restrict__ out,
                const float* __restrict__ bias, int do_ns) {
    int warp = (blockIdx.x * blockDim.x + threadIdx.x) >> 5;
    int lane = threadIdx.x & 31;
    if (warp >= NNODES) return;
    int start = g_rowptr[warp];
    int end = g_rowptr[warp + 1];
    const uint2* __restrict__ in2 = (const uint2*)in;   // 4 halves per lane

    float4 acc = make_float4(0.f, 0.f, 0.f, 0.f);
    int e = start;
    for (; e + 3 < end; e += 4) {
        int s0 = g_adj[e + 0];
        int s1 = g_adj[e + 1];
        int s2 = g_adj[e + 2];
        int s3 = g_adj[e + 3];
        uint2 v0 = __ldg(&in2[s0 * 32 + lane]);
        uint2 v1 = __ldg(&in2[s1 * 32 + lane]);
        uint2 v2 = __ldg(&in2[s2 * 32 + lane]);
        uint2 v3 = __ldg(&in2[s3 * 32 + lane]);
        float2 a, b;
        a = __half22float2(*reinterpret_cast<__half2*>(&v0.x));
        b = __half22float2(*reinterpret_cast<__half2*>(&v0.y));
        acc.x += a.x; acc.y += a.y; acc.z += b.x; acc.w += b.y;
        a = __half22float2(*reinterpret_cast<__half2*>(&v1.x));
        b = __half22float2(*reinterpret_cast<__half2*>(&v1.y));
        acc.x += a.x; acc.y += a.y; acc.z += b.x; acc.w += b.y;
        a = __half22float2(*reinterpret_cast<__half2*>(&v2.x));
        b = __half22float2(*reinterpret_cast<__half2*>(&v2.y));
        acc.x += a.x; acc.y += a.y; acc.z += b.x; acc.w += b.y;
        a = __half22float2(*reinterpret_cast<__half2*>(&v3.x));
        b = __half22float2(*reinterpret_cast<__half2*>(&v3.y));
        acc.x += a.x; acc.y += a.y; acc.z += b.x; acc.w += b.y;
    }
    for (; e < end; ++e) {
        int s = g_adj[e];
        uint2 v = __ldg(&in2[s * 32 + lane]);
        float2 a = __half22float2(*reinterpret_cast<__half2*>(&v.x));
        float2 b = __half22float2(*reinterpret_cast<__half2*>(&v.y));
        acc.x += a.x; acc.y += a.y; acc.z += b.x; acc.w += b.y;
    }
    float nd = g_nd[warp];
    float4 o;
    o.x = acc.x * nd; o.y = acc.y * nd; o.z = acc.z * nd; o.w = acc.w * nd;
    if (bias) {
        float4 bv = *(const float4*)&bias[lane * 4];
        o.x += bv.x; o.y += bv.y; o.z += bv.z; o.w += bv.w;
    }
    if (do_ns) {
        float t = g_ns[warp];
        o.x *= t; o.y *= t; o.z *= t; o.w *= t;
    }
    __half2 h0 = __floats2half2_rn(o.x, o.y);
    __half2 h1 = __floats2half2_rn(o.z, o.w);
    uint2 u;
    u.x = *reinterpret_cast<unsigned*>(&h0);
    u.y = *reinterpret_cast<unsigned*>(&h1);
    ((uint2*)out)[warp * 32 + lane] = u;
}

// final prop, half input D=64 -> fp32 out: out = nd*(A in) + b3
__global__ void __launch_bounds__(256)
prop64h_kernel(const __half* __restrict__ in, float* __restrict__ out,
               const float* __restrict__ bias) {
    int warp = (blockIdx.x * blockDim.x + threadIdx.x) >> 5;
    int lane = threadIdx.x & 31;
    if (warp >= NNODES) return;
    int start = g_rowptr[warp];
    int end = g_rowptr[warp + 1];
    const unsigned* __restrict__ in1 = (const unsigned*)in;   // 2 halves per lane

    float2 acc = make_float2(0.f, 0.f);
    int e = start;
    for (; e + 3 < end; e += 4) {
        int s0 = g_adj[e + 0];
        int s1 = g_adj[e + 1];
        int s2 = g_adj[e + 2];
        int s3 = g_adj[e + 3];
        unsigned v0 = __ldg(&in1[s0 * 32 + lane]);
        unsigned v1 = __ldg(&in1[s1 * 32 + lane]);
        unsigned v2 = __ldg(&in1[s2 * 32 + lane]);
        unsigned v3 = __ldg(&in1[s3 * 32 + lane]);
        float2 a;
        a = __half22float2(*reinterpret_cast<__half2*>(&v0)); acc.x += a.x; acc.y += a.y;
        a = __half22float2(*reinterpret_cast<__half2*>(&v1)); acc.x += a.x; acc.y += a.y;
        a = __half22float2(*reinterpret_cast<__half2*>(&v2)); acc.x += a.x; acc.y += a.y;
        a = __half22float2(*reinterpret_cast<__half2*>(&v3)); acc.x += a.x; acc.y += a.y;
    }
    for (; e < end; ++e) {
        int s = g_adj[e];
        unsigned v = __ldg(&in1[s * 32 + lane]);
        float2 a = __half22float2(*reinterpret_cast<__half2*>(&v));
        acc.x += a.x; acc.y += a.y;
    }
    float nd = g_nd[warp];
    float2 o;
    o.x = acc.x * nd + bias[lane * 2 + 0];
    o.y = acc.y * nd + bias[lane * 2 + 1];
    ((float2*)out)[warp * 32 + lane] = o;
}

// ---------------- launch -----------------------------------------------------
extern "C" void kernel_launch(void* const* d_in, const int* in_sizes, int n_in,
                              void* d_out, int out_size) {
    const float* X   = (const float*)d_in[0];
    const int*   src = (const int*)d_in[1];
    const int*   dst = (const int*)d_in[2];
    const float* W1  = (const float*)d_in[3];
    const float* b1  = (const float*)d_in[4];
    const float* W3  = (const float*)d_in[5];
    const float* b3  = (const float*)d_in[6];
    float* out = (float*)d_out;

    __half *hA, *hB, *hC;
    float *nsp;
    cudaGetSymbolAddress((void**)&hA,  g_hA);
    cudaGetSymbolAddress((void**)&hB,  g_hB);
    cudaGetSymbolAddress((void**)&hC,  g_hC);
    cudaGetSymbolAddress((void**)&nsp, g_ns);

    const int TPB = 256;
    const int edgeGrid = (NEDGES + TPB - 1) / TPB;
    const int nodeGrid = (NNODES + TPB - 1) / TPB;
    const int warpGrid = (NNODES * 32 + TPB - 1) / TPB;   // one warp per node
    const int gemmGrid = (NNODES + 127) / 128;

    // 1. CSR build + norms (multi-block scan, cursor seeded in scan3)
    zero_deg_kernel<<<nodeGrid, TPB>>>();
    degree_kernel<<<edgeGrid, TPB>>>(src, dst);
    scan1_kernel<<<SCAN_BLOCKS, 256>>>();
    scan2_kernel<<<1, 256>>>();
    scan3_norm_kernel<<<SCAN_BLOCKS, 256>>>();
    fill_csr_kernel<<<edgeGrid, TPB>>>(src, dst);

    // 2. GEMM1 (tensor core): hA = fp16( ns ⊙ (X @ W1) )
    gemm1_wmma_kernel<<<gemmGrid, 256>>>(X, W1, hA, nsp);

    // 3. GraphConv1 prop (+b1) then 4 APPNP props, pre-scaled by ns, fp16
    prop128h_kernel<<<warpGrid, TPB>>>(hA, hB, b1, 1);
    prop128h_kernel<<<warpGrid, TPB>>>(hB, hA, nullptr, 1);
    prop128h_kernel<<<warpGrid, TPB>>>(hA, hB, nullptr, 1);
    prop128h_kernel<<<warpGrid, TPB>>>(hB, hA, nullptr, 1);
    prop128h_kernel<<<warpGrid, TPB>>>(hA, hB, nullptr, 1);

    // 4. GEMM2 (tensor core): hC = (ns ⊙ h4) @ W3 == ns ⊙ (h4 @ W3)
    gemm2_wmma_kernel<<<gemmGrid, 256>>>(hB, W3, hC);

    // 5. final prop: out = nd ⊙ (A hC) + b3
    prop64h_kernel<<<warpGrid, TPB>>>(hC, out, b3);
}

// round 7
// speedup vs baseline: 2.2004x; 1.1860x over previous
#include <cuda_runtime.h>
#include <cuda_fp16.h>
#include <mma.h>

using namespace nvcuda;

// Problem constants (fixed by the dataset)
#define NNODES 50000
#define NEDGES 800000
#define DIN    256
#define DHID   128
#define DOUT   64
#define SCAN_BLOCKS 196          // ceil(50000/256)

// ---------------- static device scratch (no allocation allowed) --------------
__device__ __half g_hA[NNODES * DOUT];     // feature ping
__device__ __half g_hB[NNODES * DOUT];     // feature pong
__device__ __half g_hW13[DIN * DOUT];      // W1 @ W3, fp16
__device__ float  g_b13[DOUT];             // b1 @ W3, fp32
__device__ int    g_deg_in[NNODES];
__device__ int    g_deg_out[NNODES];
__device__ int    g_cursor[NNODES];
__device__ int    g_rowptr[NNODES + 1];
__device__ unsigned short g_adj[NEDGES];
__device__ float  g_ns[NNODES];
__device__ float  g_nd[NNODES];
__device__ int    g_blocksum[SCAN_BLOCKS];

// ---------------- CSR build ---------------------------------------------------
__global__ void zero_deg_kernel() {
    int i = blockIdx.x * blockDim.x + threadIdx.x;
    if (i < NNODES) { g_deg_in[i] = 0; g_deg_out[i] = 0; }
}

__global__ void degree_kernel(const int* __restrict__ src, const int* __restrict__ dst) {
    int e = blockIdx.x * blockDim.x + threadIdx.x;
    if (e < NEDGES) {
        atomicAdd(&g_deg_out[src[e]], 1);
        atomicAdd(&g_deg_in[dst[e]], 1);
    }
}

// phase 1: per-block exclusive scan of deg_in, block totals to g_blocksum
__global__ void __launch_bounds__(256) scan1_kernel() {
    __shared__ int s[256];
    const int tid = threadIdx.x;
    const int i = blockIdx.x * 256 + tid;
    int v = (i < NNODES) ? g_deg_in[i] : 0;
    s[tid] = v;
    __syncthreads();
#pragma unroll
    for (int off = 1; off < 256; off <<= 1) {
        int t = (tid >= off) ? s[tid - off] : 0;
        __syncthreads();
        if (tid >= off) s[tid] += t;
        __syncthreads();
    }
    if (i < NNODES) g_rowptr[i] = s[tid] - v;     // exclusive within block
    if (tid == 255) g_blocksum[blockIdx.x] = s[255];
}

// phase 2 (fused): each block REDUCES the preceding block totals (196 values,
// no serialization, no spin), then applies offset + seeds cursor + norms.
__global__ void __launch_bounds__(256) scan23_norm_kernel() {
    __shared__ int red[8];
    __shared__ int sprefix;
    const int tid = threadIdx.x;
    const int bid = blockIdx.x;
    const int lane = tid & 31;
    const int wid = tid >> 5;

    int v = (tid < bid) ? g_blocksum[tid] : 0;    // bid <= 195 < 256
#pragma unroll
    for (int off = 16; off > 0; off >>= 1)
        v += __shfl_down_sync(0xFFFFFFFF, v, off);
    if (lane == 0) red[wid] = v;
    __syncthreads();
    if (tid == 0) {
        int p = 0;
#pragma unroll
        for (int w = 0; w < 8; ++w) p += red[w];
        sprefix = p;
    }
    __syncthreads();

    const int i = bid * 256 + tid;
    if (i < NNODES) {
        int rp = g_rowptr[i] + sprefix;
        g_rowptr[i] = rp;
        g_cursor[i] = rp;                         // fill uses cursor directly
        g_ns[i] = rsqrtf((float)max(g_deg_out[i], 1));
        g_nd[i] = rsqrtf((float)max(g_deg_in[i], 1));
    }
    if (i == 0) g_rowptr[NNODES] = NEDGES;
}

__global__ void fill_csr_kernel(const int* __restrict__ src, const int* __restrict__ dst) {
    int e = blockIdx.x * blockDim.x + threadIdx.x;
    if (e < NEDGES) {
        int p = atomicAdd(&g_cursor[dst[e]], 1);
        g_adj[p] = (unsigned short)src[e];
    }
}

// ---------------- W13 = W1 @ W3 (fp32 accum -> fp16), b13 = b1 @ W3 ----------
__global__ void __launch_bounds__(256) w13_kernel(const float* __restrict__ W1,
                                                  const float* __restrict__ b1,
                                                  const float* __restrict__ W3) {
    int idx = blockIdx.x * 256 + threadIdx.x;     // 0..16383
    if (idx < DIN * DOUT) {
        int r = idx >> 6;
        int c = idx & 63;
        float s = 0.f;
#pragma unroll 8
        for (int k = 0; k < DHID; ++k)
            s = fmaf(W1[r * DHID + k], W3[k * DOUT + c], s);
        g_hW13[idx] = __float2half(s);
    }
    if (idx < DOUT) {
        float s = 0.f;
#pragma unroll 8
        for (int k = 0; k < DHID; ++k)
            s = fmaf(b1[k], W3[k * DOUT + idx], s);
        g_b13[idx] = s;
    }
}

// ---------------- GEMM (tensor core): hA = fp16( X @ W13 ) -------------------
// M=50000, K=256, N=64. A fp32 (converted in smem), B fp16. HMMA fp32 acc.
// Block tile 128x64, BK=32; 8 warps, warp tile 32x32 (4x2).
__global__ void __launch_bounds__(256)
gemm_x_w13_kernel(const float* __restrict__ A, __half* __restrict__ C) {
    constexpr int M = NNODES, K = DIN, N = DOUT;
    constexpr int BK = 32;
    __shared__ __half As[128][BK + 8];     // ldm 40 halves
    __shared__ __half Bs[BK][N + 8];       // ldm 72 halves
    __shared__ float  Sepi[8][16 * 20];

    const int tid  = threadIdx.x;
    const int lane = tid & 31;
    const int wid  = tid >> 5;
    const int wm   = wid >> 1;             // 0..3 (32 rows each)
    const int wn   = wid & 1;              // 0..1 (32 cols each)
    const int blockRow = blockIdx.x * 128;

    wmma::fragment<wmma::accumulator, 16, 16, 16, float> facc[2][2];
#pragma unroll
    for (int i = 0; i < 2; ++i)
#pragma unroll
        for (int j = 0; j < 2; ++j) wmma::fill_fragment(facc[i][j], 0.0f);

    for (int k0 = 0; k0 < K; k0 += BK) {
        // A tile: 128x32 fp32 -> half. 4096 floats = 1024 float4, 4/thread.
#pragma unroll
        for (int l = 0; l < 4; ++l) {
            int idx = tid + l * 256;
            int r  = idx >> 3;             // row 0..127
            int q  = idx & 7;              // quad 0..7
            int row = blockRow + r;
            float4 v = make_float4(0.f, 0.f, 0.f, 0.f);
            if (row < M) v = *(const float4*)&A[(long)row * K + k0 + q * 4];
            __half2 h0 = __floats2half2_rn(v.x, v.y);
            __half2 h1 = __floats2half2_rn(v.z, v.w);
            uint2 u;
            u.x = *reinterpret_cast<unsigned*>(&h0);
            u.y = *reinterpret_cast<unsigned*>(&h1);
            *(uint2*)&As[r][q * 4] = u;
        }
        // B tile: 32x64 halves = 2048 halves = 256 uint4, 1/thread.
        {
            int r = tid >> 3;              // row 0..31
            int q = tid & 7;               // 8-half group 0..7
            uint4 u = *(const uint4*)&g_hW13[(k0 + r) * N + q * 8];
            *(uint4*)&Bs[r][q * 8] = u;
        }
        __syncthreads();

#pragma unroll
        for (int kk = 0; kk < BK; kk += 16) {
            wmma::fragment<wmma::matrix_a, 16, 16, 16, __half, wmma::row_major> fa[2];
            wmma::fragment<wmma::matrix_b, 16, 16, 16, __half, wmma::row_major> fb[2];
#pragma unroll
            for (int i = 0; i < 2; ++i)
                wmma::load_matrix_sync(fa[i], &As[wm * 32 + i * 16][kk], BK + 8);
#pragma unroll
            for (int j = 0; j < 2; ++j)
                wmma::load_matrix_sync(fb[j], &Bs[kk][wn * 32 + j * 16], N + 8);
#pragma unroll
            for (int i = 0; i < 2; ++i)
#pragma unroll
                for (int j = 0; j < 2; ++j)
                    wmma::mma_sync(facc[i][j], fa[i], fb[j], facc[i][j]);
        }
        __syncthreads();
    }

    float* scratch = Sepi[wid];
#pragma unroll
    for (int i = 0; i < 2; ++i) {
#pragma unroll
        for (int j = 0; j < 2; ++j) {
            wmma::store_matrix_sync(scratch, facc[i][j], 20, wmma::mem_row_major);
            __syncwarp();
            int r = lane >> 1;
            int c = (lane & 1) * 8;
            int gm = blockRow + wm * 32 + i * 16 + r;
            if (gm < M) {
                const float* p = &scratch[r * 20 + c];
                __half2 h0 = __floats2half2_rn(p[0], p[1]);
                __half2 h1 = __floats2half2_rn(p[2], p[3]);
                __half2 h2 = __floats2half2_rn(p[4], p[5]);
                __half2 h3 = __floats2half2_rn(p[6], p[7]);
                uint4 u;
                u.x = *reinterpret_cast<unsigned*>(&h0);
                u.y = *reinterpret_cast<unsigned*>(&h1);
                u.z = *reinterpret_cast<unsigned*>(&h2);
                u.w = *reinterpret_cast<unsigned*>(&h3);
                *(uint4*)&C[(long)gm * N + wn * 32 + j * 16 + c] = u;
            }
            __syncwarp();
        }
    }
}

// ---------------- propagation, D=64 fp16 (CSR gather, warp per node) ---------
// Each lane holds 2 halves (one unsigned). Invariant: input is pre-scaled by
// ns except when EDGE_NS (prop1: input is raw X@W13; apply ns[src] per edge).
// Output: [ns *] (nd * agg + bias), fp16 (or fp32 for the final prop).
template <bool EDGE_NS, bool DO_NS, bool FP32OUT>
__global__ void __launch_bounds__(256)
prop64_kernel(const __half* __restrict__ in, void* __restrict__ out,
              const float* __restrict__ bias) {
    int node = (blockIdx.x * blockDim.x + threadIdx.x) >> 5;
    int lane = threadIdx.x & 31;
    if (node >= NNODES) return;
    int start = g_rowptr[node];
    int end = g_rowptr[node + 1];
    const unsigned* __restrict__ in1 = (const unsigned*)in;

    float2 acc = make_float2(0.f, 0.f);
    int e = start;
    for (; e + 3 < end; e += 4) {
        int s0 = g_adj[e + 0];
        int s1 = g_adj[e + 1];
        int s2 = g_adj[e + 2];
        int s3 = g_adj[e + 3];
        unsigned v0 = __ldg(&in1[s0 * 32 + lane]);
        unsigned v1 = __ldg(&in1[s1 * 32 + lane]);
        unsigned v2 = __ldg(&in1[s2 * 32 + lane]);
        unsigned v3 = __ldg(&in1[s3 * 32 + lane]);
        float2 a;
        if (EDGE_NS) {
            float t0 = __ldg(&g_ns[s0]);
            float t1 = __ldg(&g_ns[s1]);
            float t2 = __ldg(&g_ns[s2]);
            float t3 = __ldg(&g_ns[s3]);
            a = __half22float2(*reinterpret_cast<__half2*>(&v0));
            acc.x = fmaf(a.x, t0, acc.x); acc.y = fmaf(a.y, t0, acc.y);
            a = __half22float2(*reinterpret_cast<__half2*>(&v1));
            acc.x = fmaf(a.x, t1, acc.x); acc.y = fmaf(a.y, t1, acc.y);
            a = __half22float2(*reinterpret_cast<__half2*>(&v2));
            acc.x = fmaf(a.x, t2, acc.x); acc.y = fmaf(a.y, t2, acc.y);
            a = __half22float2(*reinterpret_cast<__half2*>(&v3));
            acc.x = fmaf(a.x, t3, acc.x); acc.y = fmaf(a.y, t3, acc.y);
        } else {
            a = __half22float2(*reinterpret_cast<__half2*>(&v0)); acc.x += a.x; acc.y += a.y;
            a = __half22float2(*reinterpret_cast<__half2*>(&v1)); acc.x += a.x; acc.y += a.y;
            a = __half22float2(*reinterpret_cast<__half2*>(&v2)); acc.x += a.x; acc.y += a.y;
            a = __half22float2(*reinterpret_cast<__half2*>(&v3)); acc.x += a.x; acc.y += a.y;
        }
    }
    for (; e < end; ++e) {
        int s = g_adj[e];
        unsigned v = __ldg(&in1[s * 32 + lane]);
        float2 a = __half22float2(*reinterpret_cast<__half2*>(&v));
        if (EDGE_NS) {
            float t = __ldg(&g_ns[s]);
            acc.x = fmaf(a.x, t, acc.x); acc.y = fmaf(a.y, t, acc.y);
        } else {
            acc.x += a.x; acc.y += a.y;
        }
    }
    float nd = g_nd[node];
    float2 o;
    o.x = acc.x * nd; o.y = acc.y * nd;
    if (bias) {
        float2 bv = *(const float2*)&bias[lane * 2];
        o.x += bv.x; o.y += bv.y;
    }
    if (DO_NS) {
        float t = g_ns[node];
        o.x *= t; o.y *= t;
    }
    if (FP32OUT) {
        ((float2*)out)[node * 32 + lane] = o;
    } else {
        __half2 h = __floats2half2_rn(o.x, o.y);
        ((unsigned*)out)[node * 32 + lane] = *reinterpret_cast<unsigned*>(&h);
    }
}

// ---------------- launch -----------------------------------------------------
extern "C" void kernel_launch(void* const* d_in, const int* in_sizes, int n_in,
                              void* d_out, int out_size) {
    const float* X   = (const float*)d_in[0];
    const int*   src = (const int*)d_in[1];
    const int*   dst = (const int*)d_in[2];
    const float* W1  = (const float*)d_in[3];
    const float* b1  = (const float*)d_in[4];
    const float* W3  = (const float*)d_in[5];
    const float* b3  = (const float*)d_in[6];
    float* out = (float*)d_out;

    __half *hA, *hB;
    float *b13p;
    cudaGetSymbolAddress((void**)&hA,   g_hA);
    cudaGetSymbolAddress((void**)&hB,   g_hB);
    cudaGetSymbolAddress((void**)&b13p, g_b13);

    const int TPB = 256;
    const int edgeGrid = (NEDGES + TPB - 1) / TPB;
    const int nodeGrid = (NNODES + TPB - 1) / TPB;   // == SCAN_BLOCKS
    const int warpGrid = (NNODES * 32 + TPB - 1) / TPB;
    const int gemmGrid = (NNODES + 127) / 128;

    // 1. CSR build + norms
    zero_deg_kernel<<<nodeGrid, TPB>>>();
    degree_kernel<<<edgeGrid, TPB>>>(src, dst);
    scan1_kernel<<<SCAN_BLOCKS, 256>>>();
    scan23_norm_kernel<<<SCAN_BLOCKS, 256>>>();
    fill_csr_kernel<<<edgeGrid, TPB>>>(src, dst);

    // 2. weight folding: W13 = W1@W3 (fp16), b13 = b1@W3
    w13_kernel<<<(DIN * DOUT + 255) / 256, 256>>>(W1, b1, W3);

    // 3. single GEMM: hA = fp16( X @ W13 )   [50000 x 64]
    gemm_x_w13_kernel<<<gemmGrid, 256>>>(X, hA);

    // 4. six propagations at D=64:
    //    prop1: per-edge ns (input unscaled), +b13, output pre-scaled by ns
    prop64_kernel<true,  true,  false><<<warpGrid, TPB>>>(hA, hB, b13p);
    //    props 2..5: pre-scaled invariant
    prop64_kernel<false, true,  false><<<warpGrid, TPB>>>(hB, hA, nullptr);
    prop64_kernel<false, true,  false><<<warpGrid, TPB>>>(hA, hB, nullptr);
    prop64_kernel<false, true,  false><<<warpGrid, TPB>>>(hB, hA, nullptr);
    prop64_kernel<false, true,  false><<<warpGrid, TPB>>>(hA, hB, nullptr);
    //    prop6 (final): out = nd*(A h) + b3, fp32
    prop64_kernel<false, false, true ><<<warpGrid, TPB>>>(hB, out, b3);
}

// round 8
// speedup vs baseline: 2.2972x; 1.0440x over previous
#include <cuda_runtime.h>
#include <cuda_fp16.h>
#include <mma.h>

using namespace nvcuda;

// Problem constants (fixed by the dataset)
#define NNODES 50000
#define NEDGES 800000
#define DIN    256
#define DHID   128
#define DOUT   64
#define SCAN_BLOCKS 196          // ceil(50000/256)
#define GEMM_BLOCKS 391          // ceil(50000/128)
#define DEG_BLOCKS  782          // edge grid-stride blocks in the fused kernel

// ---------------- static device scratch (no allocation allowed) --------------
__device__ __half g_hA[NNODES * DOUT];     // feature ping
__device__ __half g_hB[NNODES * DOUT];     // feature pong
__device__ __half g_hW13[DIN * DOUT];      // W1 @ W3, fp16
__device__ float  g_b13[DOUT];             // b1 @ W3, fp32
__device__ int    g_deg_in[NNODES];
__device__ int    g_deg_out[NNODES];
__device__ int    g_cursor[NNODES];
__device__ int    g_rowptr[NNODES + 1];
__device__ unsigned short g_adj[NEDGES];
__device__ float  g_ns[NNODES];
__device__ float  g_nd[NNODES];

// ---------------- K1: zero counters + fold W13/b13 ---------------------------
__global__ void __launch_bounds__(256) zero_w13_kernel(const float* __restrict__ W1,
                                                       const float* __restrict__ b1,
                                                       const float* __restrict__ W3) {
    int idx = blockIdx.x * 256 + threadIdx.x;
    if (idx < NNODES) { g_deg_in[idx] = 0; g_deg_out[idx] = 0; }
    if (idx < DIN * DOUT) {
        int r = idx >> 6;
        int c = idx & 63;
        float s = 0.f;
#pragma unroll 8
        for (int k = 0; k < DHID; ++k)
            s = fmaf(W1[r * DHID + k], W3[k * DOUT + c], s);
        g_hW13[idx] = __float2half(s);
    }
    if (idx < DOUT) {
        float s = 0.f;
#pragma unroll 8
        for (int k = 0; k < DHID; ++k)
            s = fmaf(b1[k], W3[k * DOUT + idx], s);
        g_b13[idx] = s;
    }
}

// ---------------- K2: fused GEMM (X @ W13 -> fp16) ∥ degree count ------------
// Blocks [0, GEMM_BLOCKS): tensor-core GEMM, block tile 128x64, BK=32.
// Blocks [GEMM_BLOCKS, +DEG_BLOCKS): grid-stride degree atomics over edges.
__global__ void __launch_bounds__(256)
gemm_degree_kernel(const float* __restrict__ A, __half* __restrict__ C,
                   const int* __restrict__ src, const int* __restrict__ dst) {
    if (blockIdx.x >= GEMM_BLOCKS) {
        // ---- degree path ----
        const int stride = DEG_BLOCKS * 256;
        int t = (blockIdx.x - GEMM_BLOCKS) * 256 + threadIdx.x;
        for (int e = t; e < NEDGES; e += stride) {
            atomicAdd(&g_deg_out[src[e]], 1);
            atomicAdd(&g_deg_in[dst[e]], 1);
        }
        return;
    }

    // ---- GEMM path ----
    constexpr int M = NNODES, K = DIN, N = DOUT;
    constexpr int BK = 32;
    __shared__ __half As[128][BK + 8];     // ldm 40 halves
    __shared__ __half Bs[BK][N + 8];       // ldm 72 halves
    __shared__ float  Sepi[8][16 * 20];

    const int tid  = threadIdx.x;
    const int lane = tid & 31;
    const int wid  = tid >> 5;
    const int wm   = wid >> 1;             // 0..3 (32 rows each)
    const int wn   = wid & 1;              // 0..1 (32 cols each)
    const int blockRow = blockIdx.x * 128;

    wmma::fragment<wmma::accumulator, 16, 16, 16, float> facc[2][2];
#pragma unroll
    for (int i = 0; i < 2; ++i)
#pragma unroll
        for (int j = 0; j < 2; ++j) wmma::fill_fragment(facc[i][j], 0.0f);

    for (int k0 = 0; k0 < K; k0 += BK) {
        // A tile: 128x32 fp32 -> half. 1024 float4, 4/thread.
#pragma unroll
        for (int l = 0; l < 4; ++l) {
            int idx = tid + l * 256;
            int r  = idx >> 3;             // row 0..127
            int q  = idx & 7;              // quad 0..7
            int row = blockRow + r;
            float4 v = make_float4(0.f, 0.f, 0.f, 0.f);
            if (row < M) v = *(const float4*)&A[(long)row * K + k0 + q * 4];
            __half2 h0 = __floats2half2_rn(v.x, v.y);
            __half2 h1 = __floats2half2_rn(v.z, v.w);
            uint2 u;
            u.x = *reinterpret_cast<unsigned*>(&h0);
            u.y = *reinterpret_cast<unsigned*>(&h1);
            *(uint2*)&As[r][q * 4] = u;
        }
        // B tile: 32x64 halves = 256 uint4, 1/thread.
        {
            int r = tid >> 3;              // row 0..31
            int q = tid & 7;               // 8-half group
            uint4 u = *(const uint4*)&g_hW13[(k0 + r) * N + q * 8];
            *(uint4*)&Bs[r][q * 8] = u;
        }
        __syncthreads();

#pragma unroll
        for (int kk = 0; kk < BK; kk += 16) {
            wmma::fragment<wmma::matrix_a, 16, 16, 16, __half, wmma::row_major> fa[2];
            wmma::fragment<wmma::matrix_b, 16, 16, 16, __half, wmma::row_major> fb[2];
#pragma unroll
            for (int i = 0; i < 2; ++i)
                wmma::load_matrix_sync(fa[i], &As[wm * 32 + i * 16][kk], BK + 8);
#pragma unroll
            for (int j = 0; j < 2; ++j)
                wmma::load_matrix_sync(fb[j], &Bs[kk][wn * 32 + j * 16], N + 8);
#pragma unroll
            for (int i = 0; i < 2; ++i)
#pragma unroll
                for (int j = 0; j < 2; ++j)
                    wmma::mma_sync(facc[i][j], fa[i], fb[j], facc[i][j]);
        }
        __syncthreads();
    }

    float* scratch = Sepi[wid];
#pragma unroll
    for (int i = 0; i < 2; ++i) {
#pragma unroll
        for (int j = 0; j < 2; ++j) {
            wmma::store_matrix_sync(scratch, facc[i][j], 20, wmma::mem_row_major);
            __syncwarp();
            int r = lane >> 1;
            int c = (lane & 1) * 8;
            int gm = blockRow + wm * 32 + i * 16 + r;
            if (gm < M) {
                const float* p = &scratch[r * 20 + c];
                __half2 h0 = __floats2half2_rn(p[0], p[1]);
                __half2 h1 = __floats2half2_rn(p[2], p[3]);
                __half2 h2 = __floats2half2_rn(p[4], p[5]);
                __half2 h3 = __floats2half2_rn(p[6], p[7]);
                uint4 u;
                u.x = *reinterpret_cast<unsigned*>(&h0);
                u.y = *reinterpret_cast<unsigned*>(&h1);
                u.z = *reinterpret_cast<unsigned*>(&h2);
                u.w = *reinterpret_cast<unsigned*>(&h3);
                *(uint4*)&C[(long)gm * N + wn * 32 + j * 16 + c] = u;
            }
            __syncwarp();
        }
    }
}

// ---------------- K3: single-kernel scan + norms + cursor --------------------
// Block b: (a) redundantly REDUCES deg_in[0, 256*b) (int4-vectorized; fully
// parallel, no inter-block dependency of any kind), (b) scans its own 256
// degrees, (c) writes rowptr/cursor/ns/nd.
__global__ void __launch_bounds__(256) scan_norm_kernel() {
    __shared__ int s[256];
    __shared__ int red[8];
    __shared__ int sprefix;
    const int tid = threadIdx.x;
    const int bid = blockIdx.x;
    const int lane = tid & 31;
    const int wid = tid >> 5;

    // (a) reduce preceding region: 64*bid int4 elements
    const int4* deg4 = (const int4*)g_deg_in;
    int pre = 0;
    for (int idx = tid; idx < 64 * bid; idx += 256) {
        int4 v = deg4[idx];
        pre += v.x + v.y + v.z + v.w;
    }
#pragma unroll
    for (int off = 16; off > 0; off >>= 1)
        pre += __shfl_down_sync(0xFFFFFFFF, pre, off);
    if (lane == 0) red[wid] = pre;
    __syncthreads();
    if (tid == 0) {
        int p = 0;
#pragma unroll
        for (int w = 0; w < 8; ++w) p += red[w];
        sprefix = p;
    }

    // (b) scan own 256 degrees
    const int i = bid * 256 + tid;
    int deg = (i < NNODES) ? g_deg_in[i] : 0;
    s[tid] = deg;
    __syncthreads();
#pragma unroll
    for (int off = 1; off < 256; off <<= 1) {
        int t = (tid >= off) ? s[tid - off] : 0;
        __syncthreads();
        if (tid >= off) s[tid] += t;
        __syncthreads();
    }

    // (c) outputs
    if (i < NNODES) {
        int rp = sprefix + s[tid] - deg;              // global exclusive prefix
        g_rowptr[i] = rp;
        g_cursor[i] = rp;
        g_ns[i] = rsqrtf((float)max(g_deg_out[i], 1));
        g_nd[i] = rsqrtf((float)max(deg, 1));
    }
    if (i == 0) g_rowptr[NNODES] = NEDGES;
}

// ---------------- K4: CSR fill -----------------------------------------------
__global__ void fill_csr_kernel(const int* __restrict__ src, const int* __restrict__ dst) {
    int e = blockIdx.x * blockDim.x + threadIdx.x;
    if (e < NEDGES) {
        int p = atomicAdd(&g_cursor[dst[e]], 1);
        g_adj[p] = (unsigned short)src[e];
    }
}

// ---------------- propagation, D=64 fp16 (CSR gather, warp per node) ---------
// Each lane holds 2 halves. Invariant: input is pre-scaled by ns except when
// EDGE_NS (prop1: input is raw X@W13; apply ns[src] per edge).
// Output: [ns *] (nd * agg + bias), fp16 (or fp32 for the final prop).
template <bool EDGE_NS, bool DO_NS, bool FP32OUT>
__global__ void __launch_bounds__(256)
prop64_kernel(const __half* __restrict__ in, void* __restrict__ out,
              const float* __restrict__ bias) {
    int node = (blockIdx.x * blockDim.x + threadIdx.x) >> 5;
    int lane = threadIdx.x & 31;
    if (node >= NNODES) return;
    int start = g_rowptr[node];
    int end = g_rowptr[node + 1];
    const unsigned* __restrict__ in1 = (const unsigned*)in;

    float2 acc = make_float2(0.f, 0.f);
    int e = start;
    for (; e + 3 < end; e += 4) {
        int s0 = g_adj[e + 0];
        int s1 = g_adj[e + 1];
        int s2 = g_adj[e + 2];
        int s3 = g_adj[e + 3];
        unsigned v0 = __ldg(&in1[s0 * 32 + lane]);
        unsigned v1 = __ldg(&in1[s1 * 32 + lane]);
        unsigned v2 = __ldg(&in1[s2 * 32 + lane]);
        unsigned v3 = __ldg(&in1[s3 * 32 + lane]);
        float2 a;
        if (EDGE_NS) {
            float t0 = __ldg(&g_ns[s0]);
            float t1 = __ldg(&g_ns[s1]);
            float t2 = __ldg(&g_ns[s2]);
            float t3 = __ldg(&g_ns[s3]);
            a = __half22float2(*reinterpret_cast<__half2*>(&v0));
            acc.x = fmaf(a.x, t0, acc.x); acc.y = fmaf(a.y, t0, acc.y);
            a = __half22float2(*reinterpret_cast<__half2*>(&v1));
            acc.x = fmaf(a.x, t1, acc.x); acc.y = fmaf(a.y, t1, acc.y);
            a = __half22float2(*reinterpret_cast<__half2*>(&v2));
            acc.x = fmaf(a.x, t2, acc.x); acc.y = fmaf(a.y, t2, acc.y);
            a = __half22float2(*reinterpret_cast<__half2*>(&v3));
            acc.x = fmaf(a.x, t3, acc.x); acc.y = fmaf(a.y, t3, acc.y);
        } else {
            a = __half22float2(*reinterpret_cast<__half2*>(&v0)); acc.x += a.x; acc.y += a.y;
            a = __half22float2(*reinterpret_cast<__half2*>(&v1)); acc.x += a.x; acc.y += a.y;
            a = __half22float2(*reinterpret_cast<__half2*>(&v2)); acc.x += a.x; acc.y += a.y;
            a = __half22float2(*reinterpret_cast<__half2*>(&v3)); acc.x += a.x; acc.y += a.y;
        }
    }
    for (; e < end; ++e) {
        int s = g_adj[e];
        unsigned v = __ldg(&in1[s * 32 + lane]);
        float2 a = __half22float2(*reinterpret_cast<__half2*>(&v));
        if (EDGE_NS) {
            float t = __ldg(&g_ns[s]);
            acc.x = fmaf(a.x, t, acc.x); acc.y = fmaf(a.y, t, acc.y);
        } else {
            acc.x += a.x; acc.y += a.y;
        }
    }
    float nd = g_nd[node];
    float2 o;
    o.x = acc.x * nd; o.y = acc.y * nd;
    if (bias) {
        float2 bv = *(const float2*)&bias[lane * 2];
        o.x += bv.x; o.y += bv.y;
    }
    if (DO_NS) {
        float t = g_ns[node];
        o.x *= t; o.y *= t;
    }
    if (FP32OUT) {
        ((float2*)out)[node * 32 + lane] = o;
    } else {
        __half2 h = __floats2half2_rn(o.x, o.y);
        ((unsigned*)out)[node * 32 + lane] = *reinterpret_cast<unsigned*>(&h);
    }
}

// ---------------- launch -----------------------------------------------------
extern "C" void kernel_launch(void* const* d_in, const int* in_sizes, int n_in,
                              void* d_out, int out_size) {
    const float* X   = (const float*)d_in[0];
    const int*   src = (const int*)d_in[1];
    const int*   dst = (const int*)d_in[2];
    const float* W1  = (const float*)d_in[3];
    const float* b1  = (const float*)d_in[4];
    const float* W3  = (const float*)d_in[5];
    const float* b3  = (const float*)d_in[6];
    float* out = (float*)d_out;

    __half *hA, *hB;
    float *b13p;
    cudaGetSymbolAddress((void**)&hA,   g_hA);
    cudaGetSymbolAddress((void**)&hB,   g_hB);
    cudaGetSymbolAddress((void**)&b13p, g_b13);

    const int TPB = 256;
    const int edgeGrid = (NEDGES + TPB - 1) / TPB;
    const int warpGrid = (NNODES * 32 + TPB - 1) / TPB;

    // K1: zero counters + fold W13/b13
    zero_w13_kernel<<<SCAN_BLOCKS, TPB>>>(W1, b1, W3);

    // K2: GEMM (hA = fp16(X @ W13)) overlapped with degree counting
    gemm_degree_kernel<<<GEMM_BLOCKS + DEG_BLOCKS, TPB>>>(X, hA, src, dst);

    // K3: fused scan + norms + cursor (deadlock-free redundant reduce)
    scan_norm_kernel<<<SCAN_BLOCKS, TPB>>>();

    // K4: CSR fill
    fill_csr_kernel<<<edgeGrid, TPB>>>(src, dst);

    // six propagations at D=64:
    //   prop1: per-edge ns (input unscaled), +b13, output pre-scaled by ns
    prop64_kernel<true,  true,  false><<<warpGrid, TPB>>>(hA, hB, b13p);
    //   props 2..5: pre-scaled invariant
    prop64_kernel<false, true,  false><<<warpGrid, TPB>>>(hB, hA, nullptr);
    prop64_kernel<false, true,  false><<<warpGrid, TPB>>>(hA, hB, nullptr);
    prop64_kernel<false, true,  false><<<warpGrid, TPB>>>(hB, hA, nullptr);
    prop64_kernel<false, true,  false><<<warpGrid, TPB>>>(hA, hB, nullptr);
    //   prop6 (final): out = nd*(A h) + b3, fp32
    prop64_kernel<false, false, true ><<<warpGrid, TPB>>>(hB, out, b3);
}